// round 10
// baseline (speedup 1.0000x reference)
#include <cuda_runtime.h>
#include <cuda_bf16.h>

#define CCH   11
#define NIMG  16
#define CAP   (1 << 18)
#define NBINS 2048
#define TOPK  1000
#define SORTN 4096
#define STH   0.7f

__device__ unsigned long long g_cand[NIMG][CAP];
__device__ int g_cnt[NIMG];
__device__ int g_hist[NIMG][NBINS];
__device__ int g_bstar[NIMG];

__constant__ float c_strides[5] = {8.f, 16.f, 32.f, 64.f, 128.f};

// ---- XLA logistic (current expander): 1 / (1 + exp(-x)), exp = libdevice __nv_expf ----
__device__ __forceinline__ float xla_sigmoid(float t) {
    float e = expf(-t);                       // __nv_expf, bit-identical to XLA's lowering
    return __fdiv_rn(1.0f, __fadd_rn(1.0f, e));
}

__device__ __forceinline__ int score_bin(float s) {
    int b = (int)(__fmul_rn(__fsub_rn(s, STH), 6826.0f));
    return b > (NBINS - 1) ? (NBINS - 1) : (b < 0 ? 0 : b);
}

// ---------------- kernels ----------------
__global__ void initK() {
    int i = blockIdx.x * blockDim.x + threadIdx.x;
    if (i < NIMG * NBINS) ((int*)g_hist)[i] = 0;
    if (i < NIMG) g_cnt[i] = 0;
}

__global__ void __launch_bounds__(256) passA(const float* __restrict__ cls,
                                             const float* __restrict__ ctr,
                                             const int*   __restrict__ batch) {
    __shared__ unsigned long long stage[2560];
    __shared__ int stCnt, gBase, sB0, sB1;

    int tid = threadIdx.x;
    long long base = (long long)blockIdx.x * 256;
    long long p = base + tid;

    float b   = ctr[p];
    int  img0 = batch[p];
    if (tid == 0) { sB0 = batch[base]; sB1 = batch[base + 255]; }
    __syncthreads();

    bool  bgate = (b > 0.84f);
    float sb = bgate ? xla_sigmoid(b) : 0.0f;

    for (int img = sB0; img <= sB1; img++) {
        if (tid == 0) stCnt = 0;
        __syncthreads();
        if (img0 == img && bgate) {
            const float* row = cls + p * CCH;
#pragma unroll
            for (int c = 0; c < 10; c++) {
                float a = __ldg(row + c);
                // necessary conditions for sigmoid(a)*sigmoid(b) > 0.7
                if (a > 0.84f && __fadd_rn(a, b) > 3.26f) {
                    float s = __fmul_rn(xla_sigmoid(a), sb);
                    if (s > STH) {
                        int pos = atomicAdd(&stCnt, 1);
                        unsigned idx = (unsigned)(p * CCH + c);
                        stage[pos] = ((unsigned long long)(~__float_as_uint(s)) << 32) | idx;
                    }
                }
            }
        }
        __syncthreads();
        int tot = stCnt;
        if (tid == 0) gBase = tot ? atomicAdd(&g_cnt[img], tot) : 0;
        __syncthreads();
        for (int i = tid; i < tot; i += 256) {
            int g = gBase + i;
            if (g < CAP) {
                unsigned long long k = stage[i];
                g_cand[img][g] = k;
                float s = __uint_as_float(~(unsigned)(k >> 32));
                atomicAdd(&g_hist[img][score_bin(s)], 1);
            }
        }
        __syncthreads();
    }
}

__global__ void cutK() {
    int img = threadIdx.x;
    if (img >= NIMG) return;
    int cum = 0, bst = 0;
    for (int bb = NBINS - 1; bb >= 0; bb--) {
        cum += g_hist[img][bb];
        if (cum >= TOPK) { bst = bb; break; }
    }
    g_bstar[img] = bst;
}

__global__ void __launch_bounds__(1024) finalK(const float* __restrict__ loc,
                                               const int*   __restrict__ lev,
                                               const float* __restrict__ reg,
                                               const int*   __restrict__ isz,
                                               float* __restrict__ out) {
    __shared__ __align__(16) unsigned long long uni[SORTN];  // 32KB, reused
    __shared__ float red[32];
    __shared__ int   shFi[100];
    __shared__ int   sSel, sNk;
    __shared__ float sMC;

    int img = blockIdx.x, tid = threadIdx.x;
    for (int i = tid; i < SORTN; i += 1024) uni[i] = 0xFFFFFFFFFFFFFFFFull;
    if (tid == 0) sSel = 0;
    if (tid < 100) shFi[tid] = 0;
    __syncthreads();

    int cnt = g_cnt[img]; if (cnt > CAP) cnt = CAP;
    int bst = g_bstar[img];
    for (int i = tid; i < cnt; i += 1024) {
        unsigned long long k = g_cand[img][i];
        float s = __uint_as_float(~(unsigned)(k >> 32));
        if (score_bin(s) >= bst) {
            int p = atomicAdd(&sSel, 1);
            if (p < SORTN) uni[p] = k;
        }
    }
    __syncthreads();

    // bitonic ascending: (~score_bits<<32)|idx  ==  score desc, idx asc (== top_k order)
    for (int kk = 2; kk <= SORTN; kk <<= 1)
        for (int j = kk >> 1; j > 0; j >>= 1) {
            __syncthreads();
            for (int i = tid; i < SORTN; i += 1024) {
                int x = i ^ j;
                if (x > i) {
                    unsigned long long a = uni[i], bb = uni[x];
                    if ((a > bb) == ((i & kk) == 0)) { uni[i] = bb; uni[x] = a; }
                }
            }
        }
    __syncthreads();

    int nsel = sSel; if (nsel > SORTN) nsel = SORTN;
    int nval = nsel < TOPK ? nsel : TOPK;
    unsigned long long myKey = (tid < nval) ? uni[tid] : 0ull;
    __syncthreads();

    // reuse uni as 8 arrays of 1024
    float* bX1 = (float*)uni;
    float* bY1 = bX1 + 1024;
    float* bX2 = bX1 + 2048;
    float* bY2 = bX1 + 3072;
    float* sAr = bX1 + 4096;
    float* sSc = bX1 + 5120;
    int*   sCl = (int*)(bX1 + 6144);
    int*   sKp = (int*)(bX1 + 7168);

    float X1 = 0, Y1 = 0, X2 = 0, Y2 = 0, myS = 0;
    int myCl = 0;
    if (tid < nval) {
        unsigned idx = (unsigned)myKey;
        myS = __uint_as_float(~(unsigned)(myKey >> 32));
        unsigned pt = idx / 11u;
        int c = (int)(idx - pt * 11u);
        float lx = loc[2 * (size_t)pt], ly = loc[2 * (size_t)pt + 1];
        float st = c_strides[lev[pt]];
        const float* rr = reg + 4 * (size_t)pt;
        float r0 = __fmul_rn(rr[0], st), r1 = __fmul_rn(rr[1], st);
        float r2 = __fmul_rn(rr[2], st), r3 = __fmul_rn(rr[3], st);
        float h = (float)isz[2 * img], w = (float)isz[2 * img + 1];
        float wm = __fsub_rn(w, 1.0f), hm = __fsub_rn(h, 1.0f);
        X1 = fminf(fmaxf(__fsub_rn(lx, r0), 0.0f), wm);
        Y1 = fminf(fmaxf(__fsub_rn(ly, r1), 0.0f), hm);
        X2 = fminf(fmaxf(__fadd_rn(lx, r2), 0.0f), wm);
        Y2 = fminf(fmaxf(__fadd_rn(ly, r3), 0.0f), hm);
        myCl = c + 1;
    }

    // max_coord over valid boxes
    float mx = fmaxf(fmaxf(X1, Y1), fmaxf(X2, Y2));
    for (int o = 16; o; o >>= 1) mx = fmaxf(mx, __shfl_xor_sync(0xffffffffu, mx, o));
    if ((tid & 31) == 0) red[tid >> 5] = mx;
    __syncthreads();
    if (tid < 32) {
        float v = red[tid];
        for (int o = 16; o; o >>= 1) v = fmaxf(v, __shfl_xor_sync(0xffffffffu, v, o));
        if (tid == 0) sMC = v;
    }
    __syncthreads();
    float mc1 = __fadd_rn(sMC, 1.0f);

    // offset coords + area (replicating reference rounding exactly)
    float off = __fmul_rn((float)myCl, mc1);
    float oX1 = __fadd_rn(X1, off), oY1 = __fadd_rn(Y1, off);
    float oX2 = __fadd_rn(X2, off), oY2 = __fadd_rn(Y2, off);
    float ar = __fmul_rn(fmaxf(__fadd_rn(__fsub_rn(oX2, oX1), 1.0f), 0.0f),
                         fmaxf(__fadd_rn(__fsub_rn(oY2, oY1), 1.0f), 0.0f));
    if (tid < nval) {
        bX1[tid] = X1; bY1[tid] = Y1; bX2[tid] = X2; bY2[tid] = Y2;
        sAr[tid] = ar; sSc[tid] = __fsqrt_rn(myS); sCl[tid] = myCl; sKp[tid] = 1;
    } else {
        bX1[tid] = 0; bY1[tid] = 0; bX2[tid] = 0; bY2[tid] = 0;
        sAr[tid] = 0; sSc[tid] = 0.0f; sCl[tid] = 0; sKp[tid] = 0;
    }
    __syncthreads();

    // greedy NMS, exact replication (offset boxes, 1e-9 clamp, div.rn)
    int myKeep = (tid < nval);
    for (int i = 0; i < nval; i++) {
        __syncthreads();
        if (tid > i && myKeep && sKp[i]) {
            float offj = __fmul_rn((float)sCl[i], mc1);
            float jx1 = __fadd_rn(bX1[i], offj), jy1 = __fadd_rn(bY1[i], offj);
            float jx2 = __fadd_rn(bX2[i], offj), jy2 = __fadd_rn(bY2[i], offj);
            float xx1 = fmaxf(oX1, jx1), yy1 = fmaxf(oY1, jy1);
            float xx2 = fminf(oX2, jx2), yy2 = fminf(oY2, jy2);
            float iw = fmaxf(__fadd_rn(__fsub_rn(xx2, xx1), 1.0f), 0.0f);
            float ih = fmaxf(__fadd_rn(__fsub_rn(yy2, yy1), 1.0f), 0.0f);
            float inter = __fmul_rn(iw, ih);
            float den = fmaxf(__fsub_rn(__fadd_rn(ar, sAr[i]), inter), 1e-9f);
            if (__fdiv_rn(inter, den) > 0.6f) { myKeep = 0; sKp[tid] = 0; }
        }
    }
    __syncthreads();

    // compaction: kept in order, then suppressed by ascending index (top_k-of-zeros)
    if (tid < 32) {
        int c1 = 0;
        for (int basei = 0; basei < nval && c1 < 100; basei += 32) {
            int i = basei + tid;
            int k = (i < nval) ? sKp[i] : 0;
            unsigned m = __ballot_sync(0xffffffffu, k);
            int r = c1 + __popc(m & ((1u << tid) - 1u));
            if (k && r < 100) shFi[r] = i;
            c1 += __popc(m);
        }
        int nk = c1 < 100 ? c1 : 100;
        int c2 = nk;
        for (int basei = 0; basei < nval && c2 < 100; basei += 32) {
            int i = basei + tid;
            int k = (i < nval) ? (sKp[i] == 0) : 0;
            unsigned m = __ballot_sync(0xffffffffu, k);
            int r = c2 + __popc(m & ((1u << tid) - 1u));
            if (k && r < 100) shFi[r] = i;
            c2 += __popc(m);
        }
        if (tid == 0) sNk = nk;
    }
    __syncthreads();

    // output: boxes [16,100,4] | scores [16,100] | labels [16,100] | valid [16,100]
    if (tid < 100) {
        int fi = shFi[tid];
        int nk = sNk;
        bool kept = tid < nk;
        float* ob = out + ((size_t)img * 100 + tid) * 4;
        ob[0] = bX1[fi]; ob[1] = bY1[fi]; ob[2] = bX2[fi]; ob[3] = bY2[fi];
        out[6400 + img * 100 + tid] = kept ? sSc[fi] : 0.0f;
        out[8000 + img * 100 + tid] = (float)sCl[fi];
        out[9600 + img * 100 + tid] = kept ? 1.0f : 0.0f;
    }
}

extern "C" void kernel_launch(void* const* d_in, const int* in_sizes, int n_in,
                              void* d_out, int out_size) {
    const float* loc   = (const float*)d_in[0];   // locations [M,2]
    const int*   lev   = (const int*)  d_in[1];   // levels [M]
    const int*   batch = (const int*)  d_in[2];   // batch_indices [M]
    const float* cls   = (const float*)d_in[3];   // box_cls [M,11]
    const float* reg   = (const float*)d_in[4];   // box_regression [M,4]
    const float* ctr   = (const float*)d_in[5];   // centerness [M,1]
    const int*   isz   = (const int*)  d_in[6];   // image_sizes [16,2]
    float* out = (float*)d_out;

    int M = in_sizes[1];                          // 2097152 points
    initK<<<(NIMG * NBINS + 255) / 256, 256>>>();
    passA<<<M / 256, 256>>>(cls, ctr, batch);
    cutK<<<1, 32>>>();
    finalK<<<NIMG, 1024>>>(loc, lev, reg, isz, out);
}

// round 12
// speedup vs baseline: 1.1473x; 1.1473x over previous
#include <cuda_runtime.h>
#include <cuda_bf16.h>

#define CCH   11
#define NIMG  16
#define CAP   (1 << 18)
#define NBINS 2048
#define TOPK  1000
#define SORTN 2048
#define STH   0.7f
#define KEEPBIT 0x10000

__device__ unsigned long long g_cand[NIMG][CAP];
__device__ int g_cnt[NIMG];
__device__ int g_hist[NIMG][NBINS];

__constant__ float c_strides[5] = {8.f, 16.f, 32.f, 64.f, 128.f};

// ---- XLA logistic: 1 / (1 + exp(-x)), exp = libdevice __nv_expf ----
__device__ __forceinline__ float xla_sigmoid(float t) {
    float e = expf(-t);
    return __fdiv_rn(1.0f, __fadd_rn(1.0f, e));
}

__device__ __forceinline__ int score_bin(float s) {
    int b = (int)(__fmul_rn(__fsub_rn(s, STH), 6826.0f));
    return b > (NBINS - 1) ? (NBINS - 1) : (b < 0 ? 0 : b);
}

// ---------------- kernels ----------------
__global__ void initK() {
    int i = blockIdx.x * blockDim.x + threadIdx.x;
    if (i < NIMG * NBINS) ((int*)g_hist)[i] = 0;
    if (i < NIMG) g_cnt[i] = 0;
}

__global__ void __launch_bounds__(256) passA(const float* __restrict__ cls,
                                             const float* __restrict__ ctr,
                                             const int*   __restrict__ batch) {
    __shared__ unsigned long long stage[2560];
    __shared__ int stCnt, gBase, sB0, sB1;

    int tid = threadIdx.x;
    long long base = (long long)blockIdx.x * 256;
    long long p = base + tid;

    float b   = ctr[p];
    int  img0 = batch[p];
    if (tid == 0) { sB0 = batch[base]; sB1 = batch[base + 255]; }
    __syncthreads();

    bool  bgate = (b > 0.84f);
    float sb = bgate ? xla_sigmoid(b) : 0.0f;

    for (int img = sB0; img <= sB1; img++) {
        if (tid == 0) stCnt = 0;
        __syncthreads();
        if (img0 == img && bgate) {
            const float* row = cls + p * CCH;
#pragma unroll
            for (int c = 0; c < 10; c++) {
                float a = __ldg(row + c);
                // necessary conditions for sigmoid(a)*sigmoid(b) > 0.7
                if (a > 0.84f && __fadd_rn(a, b) > 3.26f) {
                    float s = __fmul_rn(xla_sigmoid(a), sb);
                    if (s > STH) {
                        int pos = atomicAdd(&stCnt, 1);
                        unsigned idx = (unsigned)(p * CCH + c);
                        stage[pos] = ((unsigned long long)(~__float_as_uint(s)) << 32) | idx;
                    }
                }
            }
        }
        __syncthreads();
        int tot = stCnt;
        if (tid == 0) gBase = tot ? atomicAdd(&g_cnt[img], tot) : 0;
        __syncthreads();
        for (int i = tid; i < tot; i += 256) {
            int g = gBase + i;
            if (g < CAP) {
                unsigned long long k = stage[i];
                g_cand[img][g] = k;
                float s = __uint_as_float(~(unsigned)(k >> 32));
                atomicAdd(&g_hist[img][score_bin(s)], 1);
            }
        }
        __syncthreads();
    }
}

__global__ void __launch_bounds__(1024) finalK(const float* __restrict__ loc,
                                               const int*   __restrict__ lev,
                                               const float* __restrict__ reg,
                                               const int*   __restrict__ isz,
                                               float* __restrict__ out) {
    __shared__ __align__(16) unsigned long long uni[SORTN];  // 16KB (sort keys -> 4 float arrays)
    __shared__ __align__(16) int hsh[NBINS];                 // 8KB  (hist -> area + class|keep)
    __shared__ float red[32];
    __shared__ int   warpExcl[32];
    __shared__ int   sSel, sBst, sNk;
    __shared__ float sMC;

    int img = blockIdx.x, tid = threadIdx.x;
    int lane = tid & 31, wid = tid >> 5;

    // phase 1: init + load histogram
    for (int i = tid; i < SORTN; i += 1024) uni[i] = 0xFFFFFFFFFFFFFFFFull;
    for (int i = tid; i < NBINS; i += 1024) hsh[i] = g_hist[img][i];
    if (tid == 0) { sSel = 0; sBst = 0; }
    __syncthreads();

    // phase 2: cutoff bin (warp 0): chunk sums from top + shfl prefix + one serial walk
    if (tid < 32) {
        int basebin = NBINS - 64 * (lane + 1);
        int csum = 0;
#pragma unroll
        for (int j = 0; j < 64; j++) csum += hsh[basebin + j];
        int pre = csum;
#pragma unroll
        for (int o = 1; o < 32; o <<= 1) {
            int v = __shfl_up_sync(0xffffffffu, pre, o);
            if (lane >= o) pre += v;
        }
        int excl = pre - csum;
        if (excl < TOPK && pre >= TOPK) {     // exactly one lane crosses
            int cum = excl;
            for (int bb = basebin + 63; bb >= basebin; bb--) {
                cum += hsh[bb];
                if (cum >= TOPK) { sBst = bb; break; }
            }
        }
    }
    __syncthreads();

    // phase 3: select candidates with bin >= bst (ballot-aggregated)
    int cnt = g_cnt[img]; if (cnt > CAP) cnt = CAP;
    int bst = sBst;
    int cntR = (cnt + 1023) & ~1023;
    for (int i = tid; i < cntR; i += 1024) {
        unsigned long long k = 0;
        bool c = false;
        if (i < cnt) {
            k = g_cand[img][i];
            float s = __uint_as_float(~(unsigned)(k >> 32));
            c = (score_bin(s) >= bst);
        }
        unsigned m = __ballot_sync(0xffffffffu, c);
        if (m) {
            int bp = 0;
            int leader = __ffs(m) - 1;
            if (lane == leader) bp = atomicAdd(&sSel, __popc(m));
            bp = __shfl_sync(0xffffffffu, bp, leader);
            if (c) {
                int pos = bp + __popc(m & ((1u << lane) - 1u));
                if (pos < SORTN) uni[pos] = k;
            }
        }
    }
    __syncthreads();

    // phase 4: bitonic ascending: (~score_bits<<32)|idx == score desc, idx asc (top_k order)
    for (int kk = 2; kk <= SORTN; kk <<= 1)
        for (int j = kk >> 1; j > 0; j >>= 1) {
            __syncthreads();
            for (int i = tid; i < SORTN; i += 1024) {
                int x = i ^ j;
                if (x > i) {
                    unsigned long long a = uni[i], bb = uni[x];
                    if ((a > bb) == ((i & kk) == 0)) { uni[i] = bb; uni[x] = a; }
                }
            }
        }
    __syncthreads();

    int nsel = sSel; if (nsel > SORTN) nsel = SORTN;
    int nval = nsel < TOPK ? nsel : TOPK;
    unsigned long long myKey = (tid < nval) ? uni[tid] : 0ull;
    __syncthreads();

    // phase 5: decode box (reference rounding)
    float X1 = 0, Y1 = 0, X2 = 0, Y2 = 0, myS = 0;
    int myCl = 0;
    if (tid < nval) {
        unsigned idx = (unsigned)myKey;
        myS = __uint_as_float(~(unsigned)(myKey >> 32));
        unsigned pt = idx / 11u;
        int c = (int)(idx - pt * 11u);
        float lx = loc[2 * (size_t)pt], ly = loc[2 * (size_t)pt + 1];
        float st = c_strides[lev[pt]];
        const float* rr = reg + 4 * (size_t)pt;
        float r0 = __fmul_rn(rr[0], st), r1 = __fmul_rn(rr[1], st);
        float r2 = __fmul_rn(rr[2], st), r3 = __fmul_rn(rr[3], st);
        float h = (float)isz[2 * img], w = (float)isz[2 * img + 1];
        float wm = __fsub_rn(w, 1.0f), hm = __fsub_rn(h, 1.0f);
        X1 = fminf(fmaxf(__fsub_rn(lx, r0), 0.0f), wm);
        Y1 = fminf(fmaxf(__fsub_rn(ly, r1), 0.0f), hm);
        X2 = fminf(fmaxf(__fadd_rn(lx, r2), 0.0f), wm);
        Y2 = fminf(fmaxf(__fadd_rn(ly, r3), 0.0f), hm);
        myCl = c + 1;
    }

    // max_coord over valid boxes (invalid contribute 0)
    float mx = fmaxf(fmaxf(X1, Y1), fmaxf(X2, Y2));
    for (int o = 16; o; o >>= 1) mx = fmaxf(mx, __shfl_xor_sync(0xffffffffu, mx, o));
    if (lane == 0) red[wid] = mx;
    __syncthreads();
    if (tid < 32) {
        float v = red[lane];
        for (int o = 16; o; o >>= 1) v = fmaxf(v, __shfl_xor_sync(0xffffffffu, v, o));
        if (tid == 0) sMC = v;
    }
    __syncthreads();
    float mc1 = __fadd_rn(sMC, 1.0f);

    // phase 6: offset coords + offset area (reference rounding), publish to shared
    float* aX1 = (float*)uni;          // offset coords (4 x 1024 floats = 16KB)
    float* aY1 = aX1 + 1024;
    float* aX2 = aX1 + 2048;
    float* aY2 = aX1 + 3072;
    float* aAr = (float*)hsh;          // offset area
    int*   aCK = hsh + 1024;           // class | KEEPBIT

    float off = __fmul_rn((float)myCl, mc1);
    float oX1 = __fadd_rn(X1, off), oY1 = __fadd_rn(Y1, off);
    float oX2 = __fadd_rn(X2, off), oY2 = __fadd_rn(Y2, off);
    float ar = __fmul_rn(fmaxf(__fadd_rn(__fsub_rn(oX2, oX1), 1.0f), 0.0f),
                         fmaxf(__fadd_rn(__fsub_rn(oY2, oY1), 1.0f), 0.0f));
    aX1[tid] = oX1; aY1[tid] = oY1; aX2[tid] = oX2; aY2[tid] = oY2;
    aAr[tid] = ar;
    aCK[tid] = (tid < nval) ? (myCl | KEEPBIT) : 0;
    __syncthreads();

    // phase 7: greedy NMS. Cross-class IoU is exactly 0 (offset separation) -> class gate.
    int myKeep = (tid < nval);
    for (int i = 0; i < nval; i++) {
        __syncthreads();
        int cki = aCK[i];
        if (cki & KEEPBIT) {
            if (myKeep && tid > i && (cki & 0xffff) == myCl) {
                float xx1 = fmaxf(oX1, aX1[i]), yy1 = fmaxf(oY1, aY1[i]);
                float xx2 = fminf(oX2, aX2[i]), yy2 = fminf(oY2, aY2[i]);
                float iw = fmaxf(__fadd_rn(__fsub_rn(xx2, xx1), 1.0f), 0.0f);
                float ih = fmaxf(__fadd_rn(__fsub_rn(yy2, yy1), 1.0f), 0.0f);
                float inter = __fmul_rn(iw, ih);
                float den = fmaxf(__fsub_rn(__fadd_rn(ar, aAr[i]), inter), 1e-9f);
                if (__fdiv_rn(inter, den) > 0.6f) { myKeep = 0; aCK[tid] = myCl; }
            }
        }
    }
    __syncthreads();

    // phase 8: rank-based output. Kept entries first (array order == top_k order),
    // then suppressed (value 0) by ascending index — replicates top_k fill.
    int kept = (tid < nval) ? myKeep : 0;
    unsigned km = __ballot_sync(0xffffffffu, kept);
    if (lane == 0) warpExcl[wid] = __popc(km);
    __syncthreads();
    if (tid < 32) {
        int v = warpExcl[lane];
        int pre = v;
#pragma unroll
        for (int o = 1; o < 32; o <<= 1) {
            int u = __shfl_up_sync(0xffffffffu, pre, o);
            if (lane >= o) pre += u;
        }
        warpExcl[lane] = pre - v;                  // exclusive
        if (lane == 31) sNk = pre;                 // total kept
    }
    __syncthreads();
    int keptBefore = warpExcl[wid] + __popc(km & ((1u << lane) - 1u));
    int nkTot = sNk;

    if (tid < nval) {
        int r = kept ? keptBefore : (nkTot + tid - keptBefore);
        if (r < 100) {
            float* ob = out + ((size_t)img * 100 + r) * 4;
            ob[0] = X1; ob[1] = Y1; ob[2] = X2; ob[3] = Y2;
            out[6400 + img * 100 + r] = kept ? __fsqrt_rn(myS) : 0.0f;
            out[8000 + img * 100 + r] = (float)myCl;
            out[9600 + img * 100 + r] = kept ? 1.0f : 0.0f;
        }
    }
}

extern "C" void kernel_launch(void* const* d_in, const int* in_sizes, int n_in,
                              void* d_out, int out_size) {
    const float* loc   = (const float*)d_in[0];   // locations [M,2]
    const int*   lev   = (const int*)  d_in[1];   // levels [M]
    const int*   batch = (const int*)  d_in[2];   // batch_indices [M]
    const float* cls   = (const float*)d_in[3];   // box_cls [M,11]
    const float* reg   = (const float*)d_in[4];   // box_regression [M,4]
    const float* ctr   = (const float*)d_in[5];   // centerness [M,1]
    const int*   isz   = (const int*)  d_in[6];   // image_sizes [16,2]
    float* out = (float*)d_out;

    int M = in_sizes[1];                          // 2097152 points
    initK<<<(NIMG * NBINS + 255) / 256, 256>>>();
    passA<<<M / 256, 256>>>(cls, ctr, batch);
    finalK<<<NIMG, 1024>>>(loc, lev, reg, isz, out);
}

// round 14
// speedup vs baseline: 2.0790x; 1.8121x over previous
#include <cuda_runtime.h>
#include <cuda_bf16.h>

#define CCH   11
#define NIMG  16
#define CAP   (1 << 18)
#define NBINS 2048
#define TOPK  1000
#define SORTN 2048
#define STH   0.7f

__device__ unsigned long long g_cand[NIMG][CAP];
__device__ int g_cnt[NIMG];
__device__ int g_hist[NIMG][NBINS];

__constant__ float c_strides[5] = {8.f, 16.f, 32.f, 64.f, 128.f};

// ---- XLA logistic: 1 / (1 + exp(-x)), exp = libdevice __nv_expf ----
__device__ __forceinline__ float xla_sigmoid(float t) {
    float e = expf(-t);
    return __fdiv_rn(1.0f, __fadd_rn(1.0f, e));
}

__device__ __forceinline__ int score_bin(float s) {
    int b = (int)(__fmul_rn(__fsub_rn(s, STH), 6826.0f));
    return b > (NBINS - 1) ? (NBINS - 1) : (b < 0 ? 0 : b);
}

// ---------------- kernels ----------------
__global__ void initK() {
    int i = blockIdx.x * blockDim.x + threadIdx.x;
    if (i < NIMG * NBINS) ((int*)g_hist)[i] = 0;
    if (i < NIMG) g_cnt[i] = 0;
}

__global__ void __launch_bounds__(256) passA(const float* __restrict__ cls,
                                             const float* __restrict__ ctr,
                                             const int*   __restrict__ batch) {
    __shared__ unsigned long long stage[2560];
    __shared__ int stCnt, gBase, sB0, sB1;

    int tid = threadIdx.x;
    long long base = (long long)blockIdx.x * 256;
    long long p = base + tid;

    float b   = ctr[p];
    int  img0 = batch[p];
    if (tid == 0) { sB0 = batch[base]; sB1 = batch[base + 255]; }
    __syncthreads();

    bool  bgate = (b > 0.84f);
    float sb = bgate ? xla_sigmoid(b) : 0.0f;

    for (int img = sB0; img <= sB1; img++) {
        if (tid == 0) stCnt = 0;
        __syncthreads();
        if (img0 == img && bgate) {
            const float* row = cls + p * CCH;
#pragma unroll
            for (int c = 0; c < 10; c++) {
                float a = __ldg(row + c);
                // necessary conditions for sigmoid(a)*sigmoid(b) > 0.7
                if (a > 0.84f && __fadd_rn(a, b) > 3.26f) {
                    float s = __fmul_rn(xla_sigmoid(a), sb);
                    if (s > STH) {
                        int pos = atomicAdd(&stCnt, 1);
                        unsigned idx = (unsigned)(p * CCH + c);
                        stage[pos] = ((unsigned long long)(~__float_as_uint(s)) << 32) | idx;
                    }
                }
            }
        }
        __syncthreads();
        int tot = stCnt;
        if (tid == 0) gBase = tot ? atomicAdd(&g_cnt[img], tot) : 0;
        __syncthreads();
        for (int i = tid; i < tot; i += 256) {
            int g = gBase + i;
            if (g < CAP) {
                unsigned long long k = stage[i];
                g_cand[img][g] = k;
                float s = __uint_as_float(~(unsigned)(k >> 32));
                atomicAdd(&g_hist[img][score_bin(s)], 1);
            }
        }
        __syncthreads();
    }
}

__global__ void __launch_bounds__(1024) finalK(const float* __restrict__ loc,
                                               const int*   __restrict__ lev,
                                               const float* __restrict__ reg,
                                               const int*   __restrict__ isz,
                                               float* __restrict__ out) {
    __shared__ __align__(16) unsigned long long uni[SORTN];  // 16KB (sort keys -> 4 float arrays)
    __shared__ __align__(16) int hsh[NBINS];                 // 8KB  (hist -> area + class bytes)
    __shared__ float red[32];
    __shared__ int   warpExcl[32];
    __shared__ unsigned kwArr[32];
    __shared__ int   sSel, sBst, sNk;
    __shared__ float sMC;

    int img = blockIdx.x, tid = threadIdx.x;
    int lane = tid & 31, wid = tid >> 5;

    // phase 1: init + load histogram
    for (int i = tid; i < SORTN; i += 1024) uni[i] = 0xFFFFFFFFFFFFFFFFull;
    for (int i = tid; i < NBINS; i += 1024) hsh[i] = g_hist[img][i];
    if (tid == 0) { sSel = 0; sBst = 0; }
    __syncthreads();

    // phase 2: cutoff bin (warp 0): chunk sums from top + shfl prefix + one serial walk
    if (tid < 32) {
        int basebin = NBINS - 64 * (lane + 1);
        int csum = 0;
#pragma unroll
        for (int j = 0; j < 64; j++) csum += hsh[basebin + j];
        int pre = csum;
#pragma unroll
        for (int o = 1; o < 32; o <<= 1) {
            int v = __shfl_up_sync(0xffffffffu, pre, o);
            if (lane >= o) pre += v;
        }
        int excl = pre - csum;
        if (excl < TOPK && pre >= TOPK) {     // exactly one lane crosses
            int cum = excl;
            for (int bb = basebin + 63; bb >= basebin; bb--) {
                cum += hsh[bb];
                if (cum >= TOPK) { sBst = bb; break; }
            }
        }
    }
    __syncthreads();

    // phase 3: select candidates with bin >= bst (ballot-aggregated)
    int cnt = g_cnt[img]; if (cnt > CAP) cnt = CAP;
    int bst = sBst;
    int cntR = (cnt + 1023) & ~1023;
    for (int i = tid; i < cntR; i += 1024) {
        unsigned long long k = 0;
        bool c = false;
        if (i < cnt) {
            k = g_cand[img][i];
            float s = __uint_as_float(~(unsigned)(k >> 32));
            c = (score_bin(s) >= bst);
        }
        unsigned m = __ballot_sync(0xffffffffu, c);
        if (m) {
            int bp = 0;
            int leader = __ffs(m) - 1;
            if (lane == leader) bp = atomicAdd(&sSel, __popc(m));
            bp = __shfl_sync(0xffffffffu, bp, leader);
            if (c) {
                int pos = bp + __popc(m & ((1u << lane) - 1u));
                if (pos < SORTN) uni[pos] = k;
            }
        }
    }
    __syncthreads();

    // phase 4: bitonic ascending: (~score_bits<<32)|idx == score desc, idx asc (top_k order)
    for (int kk = 2; kk <= SORTN; kk <<= 1)
        for (int j = kk >> 1; j > 0; j >>= 1) {
            __syncthreads();
            for (int i = tid; i < SORTN; i += 1024) {
                int x = i ^ j;
                if (x > i) {
                    unsigned long long a = uni[i], bb = uni[x];
                    if ((a > bb) == ((i & kk) == 0)) { uni[i] = bb; uni[x] = a; }
                }
            }
        }
    __syncthreads();

    int nsel = sSel; if (nsel > SORTN) nsel = SORTN;
    int nval = nsel < TOPK ? nsel : TOPK;
    unsigned long long myKey = (tid < nval) ? uni[tid] : 0ull;
    __syncthreads();

    // phase 5: decode box (reference rounding)
    float X1 = 0, Y1 = 0, X2 = 0, Y2 = 0, myS = 0;
    int myCl = 0;
    if (tid < nval) {
        unsigned idx = (unsigned)myKey;
        myS = __uint_as_float(~(unsigned)(myKey >> 32));
        unsigned pt = idx / 11u;
        int c = (int)(idx - pt * 11u);
        float lx = loc[2 * (size_t)pt], ly = loc[2 * (size_t)pt + 1];
        float st = c_strides[lev[pt]];
        const float* rr = reg + 4 * (size_t)pt;
        float r0 = __fmul_rn(rr[0], st), r1 = __fmul_rn(rr[1], st);
        float r2 = __fmul_rn(rr[2], st), r3 = __fmul_rn(rr[3], st);
        float h = (float)isz[2 * img], w = (float)isz[2 * img + 1];
        float wm = __fsub_rn(w, 1.0f), hm = __fsub_rn(h, 1.0f);
        X1 = fminf(fmaxf(__fsub_rn(lx, r0), 0.0f), wm);
        Y1 = fminf(fmaxf(__fsub_rn(ly, r1), 0.0f), hm);
        X2 = fminf(fmaxf(__fadd_rn(lx, r2), 0.0f), wm);
        Y2 = fminf(fmaxf(__fadd_rn(ly, r3), 0.0f), hm);
        myCl = c + 1;
    }

    // max_coord over valid boxes (invalid contribute 0)
    float mx = fmaxf(fmaxf(X1, Y1), fmaxf(X2, Y2));
    for (int o = 16; o; o >>= 1) mx = fmaxf(mx, __shfl_xor_sync(0xffffffffu, mx, o));
    if (lane == 0) red[wid] = mx;
    __syncthreads();
    if (tid < 32) {
        float v = red[lane];
        for (int o = 16; o; o >>= 1) v = fmaxf(v, __shfl_xor_sync(0xffffffffu, v, o));
        if (tid == 0) sMC = v;
    }
    __syncthreads();
    float mc1 = __fadd_rn(sMC, 1.0f);

    // phase 6: offset coords + offset area (reference rounding), publish to shared
    float* aX1 = (float*)uni;          // offset coords (4 x 1024 floats = 16KB)
    float* aY1 = aX1 + 1024;
    float* aX2 = aX1 + 2048;
    float* aY2 = aX1 + 3072;
    float* aAr = (float*)hsh;          // offset area (1024 floats)
    unsigned char* aClsB = (unsigned char*)(hsh + 1024);  // class bytes (1024B)

    float off = __fmul_rn((float)myCl, mc1);
    float oX1 = __fadd_rn(X1, off), oY1 = __fadd_rn(Y1, off);
    float oX2 = __fadd_rn(X2, off), oY2 = __fadd_rn(Y2, off);
    float ar = __fmul_rn(fmaxf(__fadd_rn(__fsub_rn(oX2, oX1), 1.0f), 0.0f),
                         fmaxf(__fadd_rn(__fsub_rn(oY2, oY1), 1.0f), 0.0f));
    aX1[tid] = oX1; aY1[tid] = oY1; aX2[tid] = oX2; aY2[tid] = oY2;
    aAr[tid] = ar;
    aClsB[tid] = (unsigned char)((tid < nval) ? myCl : 0);   // 0 never matches real class
    __syncthreads();

    // phase 7: windowed greedy NMS — 1 barrier per 32 boxes.
    // Cross-class IoU is exactly 0 under the class-offset construction -> class gate.
    int myKeep = (tid < nval);
    int numWin = (nval + 31) >> 5;
    unsigned myCl4 = (unsigned)myCl * 0x01010101u;
    const unsigned* clsW = (const unsigned*)aClsB;

    for (int w = 0; w < numWin; w++) {
        int wb = w << 5;
        unsigned sup = 0;
        if (myKeep && tid > wb && wid >= w) {
            // vectorized class screen: 8 words cover the 32 window boxes
#pragma unroll
            for (int g = 0; g < 8; g++) {
                unsigned m = __vcmpeq4(clsW[(wb >> 2) + g], myCl4) & 0x01010101u;
                while (m) {
                    int bpos = __ffs(m) - 1; m &= m - 1;
                    int kk = (g << 2) + (bpos >> 3);
                    int j = wb + kk;
                    float xx1 = fmaxf(oX1, aX1[j]), yy1 = fmaxf(oY1, aY1[j]);
                    float xx2 = fminf(oX2, aX2[j]), yy2 = fminf(oY2, aY2[j]);
                    float iw = fmaxf(__fadd_rn(__fsub_rn(xx2, xx1), 1.0f), 0.0f);
                    float ih = fmaxf(__fadd_rn(__fsub_rn(yy2, yy1), 1.0f), 0.0f);
                    float inter = __fmul_rn(iw, ih);
                    float den = fmaxf(__fsub_rn(__fadd_rn(ar, aAr[j]), inter), 1e-9f);
                    if (__fdiv_rn(inter, den) > 0.6f) sup |= 1u << kk;
                }
            }
        }
        if (wid == w) {
            // resolve window-internal greedy chain in registers
            sup &= (1u << lane) - 1u;                       // only earlier window boxes
            unsigned aliveW = __ballot_sync(0xffffffffu, myKeep);
            unsigned kw = 0;
#pragma unroll 8
            for (int k = 0; k < 32; k++) {
                unsigned sk = __shfl_sync(0xffffffffu, sup, k);
                unsigned keep_k = ((aliveW >> k) & 1u) && !(sk & kw);
                kw |= keep_k << k;
            }
            myKeep = (kw >> lane) & 1u;
            if (lane == 0) kwArr[w] = kw;
        }
        __syncthreads();
        if (wid > w && myKeep) {
            if (sup & kwArr[w]) myKeep = 0;
        }
    }
    __syncthreads();

    // phase 8: rank-based output. Kept entries first (array order == top_k order),
    // then suppressed (value 0) by ascending index — replicates top_k fill.
    int kept = (tid < nval) ? myKeep : 0;
    unsigned km = __ballot_sync(0xffffffffu, kept);
    if (lane == 0) warpExcl[wid] = __popc(km);
    __syncthreads();
    if (tid < 32) {
        int v = warpExcl[lane];
        int pre = v;
#pragma unroll
        for (int o = 1; o < 32; o <<= 1) {
            int u = __shfl_up_sync(0xffffffffu, pre, o);
            if (lane >= o) pre += u;
        }
        warpExcl[lane] = pre - v;                  // exclusive
        if (lane == 31) sNk = pre;                 // total kept
    }
    __syncthreads();
    int keptBefore = warpExcl[wid] + __popc(km & ((1u << lane) - 1u));
    int nkTot = sNk;

    if (tid < nval) {
        int r = kept ? keptBefore : (nkTot + tid - keptBefore);
        if (r < 100) {
            float* ob = out + ((size_t)img * 100 + r) * 4;
            ob[0] = X1; ob[1] = Y1; ob[2] = X2; ob[3] = Y2;
            out[6400 + img * 100 + r] = kept ? __fsqrt_rn(myS) : 0.0f;
            out[8000 + img * 100 + r] = (float)myCl;
            out[9600 + img * 100 + r] = kept ? 1.0f : 0.0f;
        }
    }
}

extern "C" void kernel_launch(void* const* d_in, const int* in_sizes, int n_in,
                              void* d_out, int out_size) {
    const float* loc   = (const float*)d_in[0];   // locations [M,2]
    const int*   lev   = (const int*)  d_in[1];   // levels [M]
    const int*   batch = (const int*)  d_in[2];   // batch_indices [M]
    const float* cls   = (const float*)d_in[3];   // box_cls [M,11]
    const float* reg   = (const float*)d_in[4];   // box_regression [M,4]
    const float* ctr   = (const float*)d_in[5];   // centerness [M,1]
    const int*   isz   = (const int*)  d_in[6];   // image_sizes [16,2]
    float* out = (float*)d_out;

    int M = in_sizes[1];                          // 2097152 points
    initK<<<(NIMG * NBINS + 255) / 256, 256>>>();
    passA<<<M / 256, 256>>>(cls, ctr, batch);
    finalK<<<NIMG, 1024>>>(loc, lev, reg, isz, out);
}

// round 15
// speedup vs baseline: 2.7658x; 1.3303x over previous
#include <cuda_runtime.h>
#include <cuda_bf16.h>

#define CCH   11
#define NIMG  16
#define CAP   (1 << 18)
#define NBINS 2048
#define TOPK  1000
#define SORTN 2048
#define STH   0.7f

__device__ unsigned long long g_cand[NIMG][CAP];
__device__ int g_cnt[NIMG];
__device__ int g_hist[NIMG][NBINS];

__constant__ float c_strides[5] = {8.f, 16.f, 32.f, 64.f, 128.f};

// ---- XLA logistic: 1 / (1 + exp(-x)), exp = libdevice __nv_expf ----
__device__ __forceinline__ float xla_sigmoid(float t) {
    float e = expf(-t);
    return __fdiv_rn(1.0f, __fadd_rn(1.0f, e));
}

__device__ __forceinline__ int score_bin(float s) {
    int b = (int)(__fmul_rn(__fsub_rn(s, STH), 6826.0f));
    return b > (NBINS - 1) ? (NBINS - 1) : (b < 0 ? 0 : b);
}

// reference-rounded IoU-suppression test on offset boxes
__device__ __forceinline__ int iou_sup(float mx1, float my1, float mx2, float my2, float mar,
                                       float qx1, float qy1, float qx2, float qy2, float qar) {
    float xx1 = fmaxf(mx1, qx1), yy1 = fmaxf(my1, qy1);
    float xx2 = fminf(mx2, qx2), yy2 = fminf(my2, qy2);
    float iw = fmaxf(__fadd_rn(__fsub_rn(xx2, xx1), 1.0f), 0.0f);
    float ih = fmaxf(__fadd_rn(__fsub_rn(yy2, yy1), 1.0f), 0.0f);
    float inter = __fmul_rn(iw, ih);
    float den = fmaxf(__fsub_rn(__fadd_rn(mar, qar), inter), 1e-9f);
    return __fdiv_rn(inter, den) > 0.6f;
}

// ---------------- kernels ----------------
__global__ void initK() {
    int i = blockIdx.x * blockDim.x + threadIdx.x;
    if (i < NIMG * NBINS) ((int*)g_hist)[i] = 0;
    if (i < NIMG) g_cnt[i] = 0;
}

__global__ void __launch_bounds__(256) passA(const float* __restrict__ cls,
                                             const float* __restrict__ ctr,
                                             const int*   __restrict__ batch) {
    __shared__ __align__(16) float4 shv[704];            // 256 rows x 11 floats, coalesced staged
    __shared__ unsigned long long stage[2560];
    __shared__ int stCnt, gBase, sB0, sB1;

    int tid = threadIdx.x;
    long long base = (long long)blockIdx.x * 256;
    long long p = base + tid;

    const float4* src = (const float4*)(cls + base * CCH);
#pragma unroll
    for (int i = tid; i < 704; i += 256) shv[i] = src[i];
    float b   = ctr[p];
    int  img0 = batch[p];
    if (tid == 0) { sB0 = batch[base]; sB1 = batch[base + 255]; }
    __syncthreads();

    const float* shCls = (const float*)shv;
    bool  bgate = (b > 0.84f);
    float sb = bgate ? xla_sigmoid(b) : 0.0f;

    for (int img = sB0; img <= sB1; img++) {
        if (tid == 0) stCnt = 0;
        __syncthreads();
        if (img0 == img && bgate) {
#pragma unroll
            for (int c = 0; c < 10; c++) {
                float a = shCls[tid * CCH + c];
                // necessary conditions for sigmoid(a)*sigmoid(b) > 0.7 (log-concavity)
                if (a > 0.84f && __fadd_rn(a, b) > 3.26f) {
                    float s = __fmul_rn(xla_sigmoid(a), sb);
                    if (s > STH) {
                        int pos = atomicAdd(&stCnt, 1);
                        unsigned idx = (unsigned)(p * CCH + c);
                        stage[pos] = ((unsigned long long)(~__float_as_uint(s)) << 32) | idx;
                    }
                }
            }
        }
        __syncthreads();
        int tot = stCnt;
        if (tid == 0) gBase = tot ? atomicAdd(&g_cnt[img], tot) : 0;
        __syncthreads();
        for (int i = tid; i < tot; i += 256) {
            int g = gBase + i;
            if (g < CAP) {
                unsigned long long k = stage[i];
                g_cand[img][g] = k;
                float s = __uint_as_float(~(unsigned)(k >> 32));
                atomicAdd(&g_hist[img][score_bin(s)], 1);
            }
        }
        __syncthreads();
    }
}

__global__ void __launch_bounds__(1024) finalK(const float* __restrict__ loc,
                                               const int*   __restrict__ lev,
                                               const float* __restrict__ reg,
                                               const int*   __restrict__ isz,
                                               float* __restrict__ out) {
    __shared__ __align__(16) unsigned long long uni[SORTN];  // 16KB: sort keys -> pX1..pY2
    __shared__ __align__(16) int hsh[NBINS];                 // 8KB:  hist -> pAr + pOrig
    __shared__ float red[32];
    __shared__ int   warpExcl[32];
    __shared__ int   wcnt[32][10];
    __shared__ int   warpPre[32][10];
    __shared__ int   classTot[10];
    __shared__ int   classBase[11];
    __shared__ unsigned kmaskS[10][32];
    __shared__ unsigned char kf[1024];
    __shared__ int   sSel, sBst, sNk;
    __shared__ float sMC;

    int img = blockIdx.x, tid = threadIdx.x;
    int lane = tid & 31, wid = tid >> 5;

    // phase 1: init + load histogram
    for (int i = tid; i < SORTN; i += 1024) uni[i] = 0xFFFFFFFFFFFFFFFFull;
    for (int i = tid; i < NBINS; i += 1024) hsh[i] = g_hist[img][i];
    if (tid == 0) { sSel = 0; sBst = 0; }
    __syncthreads();

    // phase 2: cutoff bin (warp 0)
    if (tid < 32) {
        int basebin = NBINS - 64 * (lane + 1);
        int csum = 0;
#pragma unroll
        for (int j = 0; j < 64; j++) csum += hsh[basebin + j];
        int pre = csum;
#pragma unroll
        for (int o = 1; o < 32; o <<= 1) {
            int v = __shfl_up_sync(0xffffffffu, pre, o);
            if (lane >= o) pre += v;
        }
        int excl = pre - csum;
        if (excl < TOPK && pre >= TOPK) {
            int cum = excl;
            for (int bb = basebin + 63; bb >= basebin; bb--) {
                cum += hsh[bb];
                if (cum >= TOPK) { sBst = bb; break; }
            }
        }
    }
    __syncthreads();

    // phase 3: select candidates with bin >= bst
    int cnt = g_cnt[img]; if (cnt > CAP) cnt = CAP;
    int bst = sBst;
    int cntR = (cnt + 1023) & ~1023;
    for (int i = tid; i < cntR; i += 1024) {
        unsigned long long k = 0;
        bool c = false;
        if (i < cnt) {
            k = g_cand[img][i];
            float s = __uint_as_float(~(unsigned)(k >> 32));
            c = (score_bin(s) >= bst);
        }
        unsigned m = __ballot_sync(0xffffffffu, c);
        if (m) {
            int bp = 0;
            int leader = __ffs(m) - 1;
            if (lane == leader) bp = atomicAdd(&sSel, __popc(m));
            bp = __shfl_sync(0xffffffffu, bp, leader);
            if (c) {
                int pos = bp + __popc(m & ((1u << lane) - 1u));
                if (pos < SORTN) uni[pos] = k;
            }
        }
    }
    __syncthreads();

    // phase 4: bitonic sort (score desc, idx asc == top_k order)
    for (int kk = 2; kk <= SORTN; kk <<= 1)
        for (int j = kk >> 1; j > 0; j >>= 1) {
            __syncthreads();
            for (int i = tid; i < SORTN; i += 1024) {
                int x = i ^ j;
                if (x > i) {
                    unsigned long long a = uni[i], bb = uni[x];
                    if ((a > bb) == ((i & kk) == 0)) { uni[i] = bb; uni[x] = a; }
                }
            }
        }
    __syncthreads();

    int nsel = sSel; if (nsel > SORTN) nsel = SORTN;
    int nval = nsel < TOPK ? nsel : TOPK;
    unsigned long long myKey = (tid < nval) ? uni[tid] : 0ull;
    __syncthreads();

    // phase 5: decode box (reference rounding)
    float X1 = 0, Y1 = 0, X2 = 0, Y2 = 0, myS = 0;
    int myCl = 0;
    if (tid < nval) {
        unsigned idx = (unsigned)myKey;
        myS = __uint_as_float(~(unsigned)(myKey >> 32));
        unsigned pt = idx / 11u;
        int c = (int)(idx - pt * 11u);
        float lx = loc[2 * (size_t)pt], ly = loc[2 * (size_t)pt + 1];
        float st = c_strides[lev[pt]];
        const float* rr = reg + 4 * (size_t)pt;
        float r0 = __fmul_rn(rr[0], st), r1 = __fmul_rn(rr[1], st);
        float r2 = __fmul_rn(rr[2], st), r3 = __fmul_rn(rr[3], st);
        float h = (float)isz[2 * img], w = (float)isz[2 * img + 1];
        float wm = __fsub_rn(w, 1.0f), hm = __fsub_rn(h, 1.0f);
        X1 = fminf(fmaxf(__fsub_rn(lx, r0), 0.0f), wm);
        Y1 = fminf(fmaxf(__fsub_rn(ly, r1), 0.0f), hm);
        X2 = fminf(fmaxf(__fadd_rn(lx, r2), 0.0f), wm);
        Y2 = fminf(fmaxf(__fadd_rn(ly, r3), 0.0f), hm);
        myCl = c + 1;
    }

    // max_coord over valid boxes
    float mx = fmaxf(fmaxf(X1, Y1), fmaxf(X2, Y2));
    for (int o = 16; o; o >>= 1) mx = fmaxf(mx, __shfl_xor_sync(0xffffffffu, mx, o));
    if (lane == 0) red[wid] = mx;
    __syncthreads();
    if (tid < 32) {
        float v = red[lane];
        for (int o = 16; o; o >>= 1) v = fmaxf(v, __shfl_xor_sync(0xffffffffu, v, o));
        if (tid == 0) sMC = v;
    }
    __syncthreads();
    float mc1 = __fadd_rn(sMC, 1.0f);

    // phase 6: offset coords + area (reference rounding), stable partition by class
    float* pX1 = (float*)uni;
    float* pY1 = pX1 + 1024;
    float* pX2 = pX1 + 2048;
    float* pY2 = pX1 + 3072;
    float* pAr = (float*)hsh;
    unsigned short* pOrig = (unsigned short*)(hsh + 1024);

    float off = __fmul_rn((float)myCl, mc1);
    float oX1 = __fadd_rn(X1, off), oY1 = __fadd_rn(Y1, off);
    float oX2 = __fadd_rn(X2, off), oY2 = __fadd_rn(Y2, off);
    float ar = __fmul_rn(fmaxf(__fadd_rn(__fsub_rn(oX2, oX1), 1.0f), 0.0f),
                         fmaxf(__fadd_rn(__fsub_rn(oY2, oY1), 1.0f), 0.0f));

    int myIntra = 0;
#pragma unroll
    for (int c = 1; c <= 10; c++) {
        unsigned bm = __ballot_sync(0xffffffffu, myCl == c);
        if (lane == 0) wcnt[wid][c - 1] = __popc(bm);
        if (myCl == c) myIntra = __popc(bm & ((1u << lane) - 1u));
    }
    kf[tid] = 0;
    __syncthreads();
    if (tid < 10) {
        int pre = 0;
#pragma unroll 8
        for (int w = 0; w < 32; w++) { warpPre[w][tid] = pre; pre += wcnt[w][tid]; }
        classTot[tid] = pre;
    }
    __syncthreads();
    if (tid == 0) {
        int bb = 0;
#pragma unroll
        for (int c = 0; c < 10; c++) { classBase[c] = bb; bb += classTot[c]; }
        classBase[10] = bb;
    }
    __syncthreads();
    if (myCl > 0) {
        int rank = classBase[myCl - 1] + warpPre[wid][myCl - 1] + myIntra;
        pX1[rank] = oX1; pY1[rank] = oY1; pX2[rank] = oX2; pY2[rank] = oY2;
        pAr[rank] = ar;  pOrig[rank] = (unsigned short)tid;
    }
    __syncthreads();

    // phase 7: per-class warp NMS (exact: cross-class IoU is 0 by offset separation).
    // Warp w handles class w+1; no block barriers inside.
    if (wid < 10) {
        int beg = classBase[wid];
        int end = classBase[wid + 1];
        int nch = (end - beg + 31) >> 5;
        for (int t = 0; t < nch; t++) {
            int j = beg + (t << 5) + lane;
            bool valid = j < end;
            float x1 = 0, y1 = 0, x2 = 0, y2 = 0, aa = 0;
            if (valid) { x1 = pX1[j]; y1 = pY1[j]; x2 = pX2[j]; y2 = pY2[j]; aa = pAr[j]; }
            int supp = 0;
            // suppression by kept boxes of earlier chunks (broadcast reads)
            for (int e = 0; e < t; e++) {
                unsigned km = kmaskS[wid][e];
                while (km) {
                    int k = __ffs(km) - 1; km &= km - 1;
                    int q = beg + (e << 5) + k;
                    float qx1 = pX1[q], qy1 = pY1[q], qx2 = pX2[q], qy2 = pY2[q], qa = pAr[q];
                    if (valid && !supp)
                        supp |= iou_sup(x1, y1, x2, y2, aa, qx1, qy1, qx2, qy2, qa);
                }
            }
            unsigned alive = __ballot_sync(0xffffffffu, valid && !supp);
            // within-chunk pairwise sup bits
            unsigned mysup = 0;
#pragma unroll 8
            for (int k = 0; k < 32; k++) {
                float qx1 = __shfl_sync(0xffffffffu, x1, k);
                float qy1 = __shfl_sync(0xffffffffu, y1, k);
                float qx2 = __shfl_sync(0xffffffffu, x2, k);
                float qy2 = __shfl_sync(0xffffffffu, y2, k);
                float qa  = __shfl_sync(0xffffffffu, aa, k);
                if (lane > k && iou_sup(x1, y1, x2, y2, aa, qx1, qy1, qx2, qy2, qa))
                    mysup |= 1u << k;
            }
            // greedy chain within chunk
            unsigned kw = 0;
#pragma unroll 8
            for (int k = 0; k < 32; k++) {
                unsigned sk = __shfl_sync(0xffffffffu, mysup, k);
                unsigned keep_k = ((alive >> k) & 1u) && !(sk & kw);
                kw |= keep_k << k;
            }
            if (lane == 0) kmaskS[wid][t] = kw;
            __syncwarp();
            if (valid) kf[pOrig[j]] = (unsigned char)((kw >> lane) & 1u);
        }
    }
    __syncthreads();

    // phase 8: rank-based output (kept first in score order, then suppressed asc)
    int kept = (tid < nval) ? (int)kf[tid] : 0;
    unsigned km2 = __ballot_sync(0xffffffffu, kept);
    if (lane == 0) warpExcl[wid] = __popc(km2);
    __syncthreads();
    if (tid < 32) {
        int v = warpExcl[lane];
        int pre = v;
#pragma unroll
        for (int o = 1; o < 32; o <<= 1) {
            int u = __shfl_up_sync(0xffffffffu, pre, o);
            if (lane >= o) pre += u;
        }
        warpExcl[lane] = pre - v;
        if (lane == 31) sNk = pre;
    }
    __syncthreads();
    int keptBefore = warpExcl[wid] + __popc(km2 & ((1u << lane) - 1u));
    int nkTot = sNk;

    if (tid < nval) {
        int r = kept ? keptBefore : (nkTot + tid - keptBefore);
        if (r < 100) {
            float* ob = out + ((size_t)img * 100 + r) * 4;
            ob[0] = X1; ob[1] = Y1; ob[2] = X2; ob[3] = Y2;
            out[6400 + img * 100 + r] = kept ? __fsqrt_rn(myS) : 0.0f;
            out[8000 + img * 100 + r] = (float)myCl;
            out[9600 + img * 100 + r] = kept ? 1.0f : 0.0f;
        }
    }
}

extern "C" void kernel_launch(void* const* d_in, const int* in_sizes, int n_in,
                              void* d_out, int out_size) {
    const float* loc   = (const float*)d_in[0];   // locations [M,2]
    const int*   lev   = (const int*)  d_in[1];   // levels [M]
    const int*   batch = (const int*)  d_in[2];   // batch_indices [M]
    const float* cls   = (const float*)d_in[3];   // box_cls [M,11]
    const float* reg   = (const float*)d_in[4];   // box_regression [M,4]
    const float* ctr   = (const float*)d_in[5];   // centerness [M,1]
    const int*   isz   = (const int*)  d_in[6];   // image_sizes [16,2]
    float* out = (float*)d_out;

    int M = in_sizes[1];                          // 2097152 points
    initK<<<(NIMG * NBINS + 255) / 256, 256>>>();
    passA<<<M / 256, 256>>>(cls, ctr, batch);
    finalK<<<NIMG, 1024>>>(loc, lev, reg, isz, out);
}